// round 4
// baseline (speedup 1.0000x reference)
#include <cuda_runtime.h>
#include <cuda_bf16.h>

// SoftVectorQuantizer on GB300 — Round 1 fp32 baseline.
//
// Math: softmax(-dists) row-wise; ||z||^2 cancels, so
//   l_k    = 2*z.e_k - ||e_k||^2          (logits, tiny spread -> no max sub)
//   w_k    = exp(l_k)
//   z_soft = (sum_k w_k e_k) / (sum_k w_k)
//   loss   = mean((z_soft - z)^2)
//
// Structure: per block: 64 z-rows, loop over 16 K-chunks of 64 codes:
//   phase1 GEMM 64x64x256 (logits), exp -> smem weights + denom partials,
//   phase2 GEMM 64x256x64 accumulating z_soft in registers.
// Deterministic: no float atomics anywhere (fixed-order partial sums).

#define D        256
#define KTOT     1024
#define TILE_M   64
#define KC       64
#define ZSTRIDE  65   // float4 chunks per padded smem row (260 floats)
#define WSTRIDE  68   // floats per sW row

__device__ float g_ce[KTOT];
__device__ float g_block_loss[4096];

__global__ void ce_kernel(const float* __restrict__ cb) {
    int k = blockIdx.x * blockDim.x + threadIdx.x;
    if (k < KTOT) {
        const float4* r = reinterpret_cast<const float4*>(cb + (size_t)k * D);
        float s = 0.f;
        #pragma unroll 8
        for (int i = 0; i < D / 4; i++) {
            float4 v = r[i];
            s += v.x * v.x + v.y * v.y + v.z * v.z + v.w * v.w;
        }
        g_ce[k] = s;
    }
}

extern __shared__ float smem[];

__global__ void __launch_bounds__(256, 1) svq_main(
    const float* __restrict__ z, const float* __restrict__ cb,
    float* __restrict__ out)
{
    // smem layout (floats)
    float* sZ    = smem;                      // 64 * 260
    float* sE    = sZ + TILE_M * 260;         // 64 * 260
    float* sW    = sE + KC * 260;             // 64 * 68
    float* sDenP = sW + TILE_M * WSTRIDE;     // 64 * 16
    float* sDen  = sDenP + TILE_M * 16;       // 64
    float* sRed  = sDen + TILE_M;             // 8

    const int tid = threadIdx.x;
    const int mt  = tid & 15;   // row group: rows mt + 16*i
    const int kt  = tid >> 4;   // phase1: code group; phase2: dim group

    const int rowBase = blockIdx.x * TILE_M;

    // zero denom partials
    for (int i = tid; i < TILE_M * 16; i += 256) sDenP[i] = 0.f;

    // load z tile [64][256] -> padded smem rows
    {
        const float4* g  = reinterpret_cast<const float4*>(z + (size_t)rowBase * D);
        float4*       s4 = reinterpret_cast<float4*>(sZ);
        for (int t = tid; t < TILE_M * 64; t += 256) {
            int r = t >> 6, c = t & 63;
            s4[r * ZSTRIDE + c] = g[r * 64 + c];
        }
    }

    float4 acc2[4][4];
    #pragma unroll
    for (int i = 0; i < 4; i++)
        #pragma unroll
        for (int j = 0; j < 4; j++) acc2[i][j] = make_float4(0.f, 0.f, 0.f, 0.f);

    const float4* sZ4 = reinterpret_cast<const float4*>(sZ);
    const float4* sE4 = reinterpret_cast<const float4*>(sE);

    for (int ch = 0; ch < KTOT / KC; ch++) {
        __syncthreads();  // prior phase2 done reading sE/sW; also covers init/z-load on ch=0

        // load codebook chunk [64][256] -> padded smem rows
        {
            const float4* g  = reinterpret_cast<const float4*>(cb + (size_t)ch * KC * D);
            float4*       s4 = reinterpret_cast<float4*>(sE);
            for (int t = tid; t < KC * 64; t += 256) {
                int r = t >> 6, c = t & 63;
                s4[r * ZSTRIDE + c] = g[r * 64 + c];
            }
        }
        __syncthreads();

        // ---- phase 1: logits tile 64x64 (4x4 register tile per thread) ----
        float a1[4][4];
        #pragma unroll
        for (int i = 0; i < 4; i++)
            #pragma unroll
            for (int j = 0; j < 4; j++) a1[i][j] = 0.f;

        #pragma unroll 2
        for (int d4 = 0; d4 < D / 4; d4++) {
            float4 av[4], bv[4];
            #pragma unroll
            for (int i = 0; i < 4; i++) av[i] = sZ4[(mt + 16 * i) * ZSTRIDE + d4];
            #pragma unroll
            for (int j = 0; j < 4; j++) bv[j] = sE4[(kt + 16 * j) * ZSTRIDE + d4];
            #pragma unroll
            for (int i = 0; i < 4; i++)
                #pragma unroll
                for (int j = 0; j < 4; j++) {
                    a1[i][j] += av[i].x * bv[j].x;
                    a1[i][j] += av[i].y * bv[j].y;
                    a1[i][j] += av[i].z * bv[j].z;
                    a1[i][j] += av[i].w * bv[j].w;
                }
        }

        // exp, stash weights, accumulate per-(row,kt) denominator partials
        #pragma unroll
        for (int i = 0; i < 4; i++) {
            float rs = 0.f;
            #pragma unroll
            for (int j = 0; j < 4; j++) {
                int   kk = kt + 16 * j;
                float l  = 2.f * a1[i][j] - g_ce[ch * KC + kk];
                float w  = __expf(l);
                sW[(mt + 16 * i) * WSTRIDE + kk] = w;
                rs += w;
            }
            sDenP[(mt + 16 * i) * 16 + kt] += rs;  // single owner per slot: deterministic
        }
        __syncthreads();

        // ---- phase 2: acc2 += W * E  (rows mt+16i, dims 16*kt..16*kt+15) ----
        #pragma unroll 2
        for (int k = 0; k < KC; k++) {
            float wv[4];
            #pragma unroll
            for (int i = 0; i < 4; i++) wv[i] = sW[(mt + 16 * i) * WSTRIDE + k];
            float4 ev[4];
            #pragma unroll
            for (int j = 0; j < 4; j++) ev[j] = sE4[k * ZSTRIDE + kt * 4 + j];
            #pragma unroll
            for (int i = 0; i < 4; i++)
                #pragma unroll
                for (int j = 0; j < 4; j++) {
                    acc2[i][j].x += wv[i] * ev[j].x;
                    acc2[i][j].y += wv[i] * ev[j].y;
                    acc2[i][j].z += wv[i] * ev[j].z;
                    acc2[i][j].w += wv[i] * ev[j].w;
                }
        }
    }
    __syncthreads();

    // finalize denominators in fixed order
    if (tid < TILE_M) {
        float s = 0.f;
        #pragma unroll
        for (int q = 0; q < 16; q++) s += sDenP[tid * 16 + q];
        sDen[tid] = s;
    }
    __syncthreads();

    // normalize, write z_soft, accumulate loss partial
    float  lsum = 0.f;
    float4* out4 = reinterpret_cast<float4*>(out);
    #pragma unroll
    for (int i = 0; i < 4; i++) {
        int    row = mt + 16 * i;
        float  inv = 1.f / sDen[row];
        size_t ob  = (size_t)(rowBase + row) * (D / 4);
        #pragma unroll
        for (int j = 0; j < 4; j++) {
            float4 v = acc2[i][j];
            v.x *= inv; v.y *= inv; v.z *= inv; v.w *= inv;
            float4 zv = sZ4[row * ZSTRIDE + kt * 4 + j];
            float dx = v.x - zv.x, dy = v.y - zv.y, dz = v.z - zv.z, dw = v.w - zv.w;
            lsum += dx * dx + dy * dy + dz * dz + dw * dw;
            out4[ob + kt * 4 + j] = v;
        }
    }

    // deterministic block reduction of loss
    #pragma unroll
    for (int off = 16; off > 0; off >>= 1)
        lsum += __shfl_down_sync(0xffffffffu, lsum, off);
    if ((tid & 31) == 0) sRed[tid >> 5] = lsum;
    __syncthreads();
    if (tid == 0) {
        float s = 0.f;
        #pragma unroll
        for (int w = 0; w < 8; w++) s += sRed[w];
        g_block_loss[blockIdx.x] = s;
    }
}

__global__ void loss_finalize(float* __restrict__ out, int nblocks,
                              float inv_nd, int loss_idx) {
    __shared__ float sh[256];
    int tid = threadIdx.x;
    float s = 0.f;
    for (int i = tid; i < nblocks; i += 256) s += g_block_loss[i];  // fixed order
    sh[tid] = s;
    __syncthreads();
    for (int off = 128; off > 0; off >>= 1) {
        if (tid < off) sh[tid] += sh[tid + off];
        __syncthreads();
    }
    if (tid == 0) out[loss_idx] = sh[0] * inv_nd;
}

extern "C" void kernel_launch(void* const* d_in, const int* in_sizes, int n_in,
                              void* d_out, int out_size) {
    const float* z  = (const float*)d_in[0];
    const float* cb = (const float*)d_in[1];
    int sz0 = in_sizes[0], sz1 = in_sizes[1];
    if (sz0 < sz1) {  // robustness: z is the big tensor
        const float* t = z; z = cb; cb = t;
        int ts = sz0; sz0 = sz1; sz1 = ts;
    }
    float* out = (float*)d_out;

    int nrows   = sz0 / D;          // 131072
    int nblocks = nrows / TILE_M;   // 2048

    const int SMEM_BYTES =
        (TILE_M * 260 + KC * 260 + TILE_M * WSTRIDE + TILE_M * 16 + TILE_M + 8)
        * (int)sizeof(float);       // ~154.9 KB

    cudaFuncSetAttribute(svq_main, cudaFuncAttributeMaxDynamicSharedMemorySize,
                         SMEM_BYTES);

    ce_kernel<<<(KTOT + 127) / 128, 128>>>(cb);
    svq_main<<<nblocks, 256, SMEM_BYTES>>>(z, cb, out);

    float inv_nd = 1.0f / ((float)nrows * (float)D);
    loss_finalize<<<1, 256>>>(out, nblocks, inv_nd, out_size - 1);
}

// round 6
// speedup vs baseline: 8.8328x; 8.8328x over previous
#include <cuda_runtime.h>
#include <cuda_fp16.h>
#include <cstdint>

// SoftVectorQuantizer R5: fp16 mma.sync (HMMA) flash-style — tcgen05 is
// unavailable (harness compiles at compute_103, no 'a' features).
// w = exp2(S - log2e*||e||^2), S = (2log2e*z).e ; z_soft = (W E)/rowsum(W)

#define D 256
#define KTOT 1024
#define TILE_M 128
#define KC 64
#define NCH 16
#define THREADS 512
#define SCLF 2.8853900817779268f
#define LOG2E 1.4426950408889634f

// smem layout (bytes)
#define OFF_CE   0        // 4KB   ce values
#define OFF_DENP 4096     // 8KB   denom partials [128][16]
#define OFF_DEN  12288    // 512B  denom final [128]
#define OFF_RED  12800    // 64B   loss partials [16]
#define OFF_W    13312    // 16KB  W tile [128][64] f16 swizzled
#define OFF_Z    29696    // 64KB  Z tile f16, 4 blocks [128][128B] swizzled
#define OFF_EB   95232    // 2 x 32KB E chunk bufs, 4 blocks [64][128B] each
#define SMEM_TOTAL 160768

#define SWZ128(o) ((o) ^ (((o) >> 3) & 0x70))

__device__ __forceinline__ uint32_t smem_u32(const void* p){
    uint32_t a; asm("{ .reg .u64 t; cvta.to.shared.u64 t, %1; cvt.u32.u64 %0, t; }":"=r"(a):"l"(p)); return a;
}
__device__ __forceinline__ float ex2(float x){ float y; asm("ex2.approx.ftz.f32 %0,%1;":"=f"(y):"f"(x)); return y; }

#define CPA16(d,s) asm volatile("cp.async.cg.shared.global [%0], [%1], 16;"::"r"(d),"l"(s):"memory")
#define CPA_COMMIT() asm volatile("cp.async.commit_group;":::"memory")
#define CPA_WAIT1() asm volatile("cp.async.wait_group 1;":::"memory")
#define CPA_WAIT0() asm volatile("cp.async.wait_group 0;":::"memory")

#define LDSM4(r,a) asm volatile("ldmatrix.sync.aligned.m8n8.x4.shared.b16 {%0,%1,%2,%3}, [%4];" \
    :"=r"((r)[0]),"=r"((r)[1]),"=r"((r)[2]),"=r"((r)[3]):"r"(a))
#define LDSM4T(r,a) asm volatile("ldmatrix.sync.aligned.m8n8.x4.trans.shared.b16 {%0,%1,%2,%3}, [%4];" \
    :"=r"((r)[0]),"=r"((r)[1]),"=r"((r)[2]),"=r"((r)[3]):"r"(a))

#define MMA(dd,aa,b0,b1) asm volatile( \
    "mma.sync.aligned.m16n8k16.row.col.f32.f16.f16.f32 {%0,%1,%2,%3},{%4,%5,%6,%7},{%8,%9},{%0,%1,%2,%3};" \
    : "+f"((dd)[0]),"+f"((dd)[1]),"+f"((dd)[2]),"+f"((dd)[3]) \
    : "r"((aa)[0]),"r"((aa)[1]),"r"((aa)[2]),"r"((aa)[3]),"r"(b0),"r"(b1))

__device__ __align__(16) __half g_eh[KTOT*D];
__device__ float g_ce2[KTOT];
__device__ float g_block_loss[1024];

__global__ void prep_cb(const float* __restrict__ cb){
    int k=blockIdx.x, d=threadIdx.x;
    float v=cb[k*D+d];
    g_eh[k*D+d]=__float2half(v);
    __shared__ float sh[256];
    sh[d]=v*v; __syncthreads();
    for(int o=128;o>0;o>>=1){ if(d<o) sh[d]+=sh[d+o]; __syncthreads(); }
    if(d==0) g_ce2[k]=sh[0]*LOG2E;
}

// 32KB codebook chunk (64 codes x 256 dims f16) -> 4 swizzled [64][128B] blocks
__device__ __forceinline__ void load_chunk(uint32_t sb,int ch,int buf,int tid){
    const char* g=(const char*)g_eh + (size_t)ch*KC*D*2;
    uint32_t eb=sb+OFF_EB+buf*32768;
    #pragma unroll
    for(int i=0;i<4;i++){
        int u=i*THREADS+tid, row=u>>5, un=u&31;
        uint32_t dst=eb+(un>>3)*8192+SWZ128((uint32_t)(row*128+(un&7)*16));
        CPA16(dst, g+(size_t)row*512+un*16);
    }
}

extern __shared__ char smem[];

__global__ void __launch_bounds__(THREADS,1) svq_hmma(
    const float* __restrict__ z, float* __restrict__ out)
{
    uint32_t sb=smem_u32(smem);
    int tid=threadIdx.x, wid=tid>>5, t=tid&31;
    int mg=wid>>2, ng=wid&3;
    size_t rowBase=(size_t)blockIdx.x*TILE_M;

    load_chunk(sb,0,0,tid); CPA_COMMIT();
    load_chunk(sb,1,1,tid); CPA_COMMIT();

    float* sCE=(float*)(smem+OFF_CE);
    for(int i=tid;i<KTOT;i+=THREADS) sCE[i]=g_ce2[i];

    { // stage Z tile -> f16 * 2log2e, 4 swizzled [128][128B] blocks
        const float4* zg=(const float4*)(z+rowBase*D);
        #pragma unroll
        for(int it=0;it<8;it++){
            int idx=it*THREADS+tid, r=idx>>5, q=idx&31;
            float4 a=zg[(size_t)r*64+q*2], b=zg[(size_t)r*64+q*2+1];
            __half2 h0=__floats2half2_rn(a.x*SCLF,a.y*SCLF), h1=__floats2half2_rn(a.z*SCLF,a.w*SCLF);
            __half2 h2=__floats2half2_rn(b.x*SCLF,b.y*SCLF), h3=__floats2half2_rn(b.z*SCLF,b.w*SCLF);
            uint4 u; u.x=*(uint32_t*)&h0; u.y=*(uint32_t*)&h1; u.z=*(uint32_t*)&h2; u.w=*(uint32_t*)&h3;
            *(uint4*)(smem+OFF_Z+(q>>3)*16384+SWZ128((uint32_t)(r*128+(q&7)*16)))=u;
        }
    }

    // per-thread ldmatrix address components (swizzled layout: row*128 + (col ^ ((row&7)<<4)))
    const uint32_t xv=(uint32_t)(t&7)<<4;               // all ldsm rows have row&7 == t&7
    const uint32_t c0=(uint32_t)(t>>4)<<4;              // lane col-byte base
    uint32_t cs[4];
    #pragma unroll
    for(int k=0;k<4;k++) cs[k]=(c0+k*32)^xv;

    const uint32_t zA0=sb+OFF_Z+(uint32_t)(32*mg+(t&15))*128;
    const uint32_t zA1=zA0+16*128;
    const uint32_t wA0=sb+OFF_W+(uint32_t)(32*mg+(t&15))*128;
    const uint32_t wA1=wA0+16*128;
    const uint32_t xw=(uint32_t)(t>>2)<<4;              // W-store swizzle (rows have row&7 == t>>2)

    float acc2[2][8][4]; float den[2][2]={{0.f,0.f},{0.f,0.f}};
    #pragma unroll
    for(int mi=0;mi<2;mi++)
        #pragma unroll
        for(int j=0;j<8;j++)
            #pragma unroll
            for(int q=0;q<4;q++) acc2[mi][j][q]=0.f;

    #pragma unroll 1
    for(int ch=0;ch<NCH;ch++){
        if(ch<NCH-1) CPA_WAIT1(); else CPA_WAIT0();
        __syncthreads();
        const uint32_t eb=sb+OFF_EB+(uint32_t)(ch&1)*32768;
        const uint32_t eB1=eb+(uint32_t)(16*ng+(t&15))*128;

        // ---- GEMM1: S[m32 x n16] ----
        float acc1[2][2][4];
        #pragma unroll
        for(int mi=0;mi<2;mi++)
            #pragma unroll
            for(int ni=0;ni<2;ni++)
                #pragma unroll
                for(int q=0;q<4;q++) acc1[mi][ni][q]=0.f;
        #pragma unroll
        for(int ks=0;ks<16;ks++){
            uint32_t a0[4],a1[4],b[4];
            uint32_t zblk=(uint32_t)(ks>>2)*16384, eblk=(uint32_t)(ks>>2)*8192, cc=cs[ks&3];
            LDSM4(a0, zA0+zblk+cc);
            LDSM4(a1, zA1+zblk+cc);
            LDSM4(b,  eB1+eblk+cc);
            MMA(acc1[0][0],a0,b[0],b[2]); MMA(acc1[0][1],a0,b[1],b[3]);
            MMA(acc1[1][0],a1,b[0],b[2]); MMA(acc1[1][1],a1,b[1],b[3]);
        }

        // ---- epilogue: w=ex2(S-ce), denom partials, pack W into smem ----
        const float* ce=sCE+ch*64;
        #pragma unroll
        for(int mi=0;mi<2;mi++){
            uint32_t r0=(uint32_t)(32*mg+16*mi+(t>>2));
            #pragma unroll
            for(int ni=0;ni<2;ni++){
                int col=16*ng+ni*8+(t&3)*2;
                float w0=ex2(acc1[mi][ni][0]-ce[col]);
                float w1=ex2(acc1[mi][ni][1]-ce[col+1]);
                float w2=ex2(acc1[mi][ni][2]-ce[col]);
                float w3=ex2(acc1[mi][ni][3]-ce[col+1]);
                den[mi][0]+=w0+w1; den[mi][1]+=w2+w3;
                __half2 p0=__floats2half2_rn(w0,w1), p1=__floats2half2_rn(w2,w3);
                uint32_t cw=((uint32_t)(col*2))^xw;
                *(uint32_t*)(smem+OFF_W+r0*128+cw)=*(uint32_t*)&p0;
                *(uint32_t*)(smem+OFF_W+(r0+8)*128+cw)=*(uint32_t*)&p1;
            }
        }
        __syncthreads();

        // ---- GEMM2: acc2[m32 x n64] += W[m32 x k64] * E[k64 x n64(block ng)] ----
        #pragma unroll
        for(int ks=0;ks<4;ks++){
            uint32_t a0[4],a1[4];
            LDSM4(a0, wA0+cs[ks]);
            LDSM4(a1, wA1+cs[ks]);
            uint32_t eRow=eb+(uint32_t)ng*8192+(uint32_t)(ks*16+(t&15))*128;
            #pragma unroll
            for(int nt=0;nt<4;nt++){
                uint32_t bt[4];
                LDSM4T(bt, eRow+cs[nt]);
                MMA(acc2[0][nt*2],  a0,bt[0],bt[1]); MMA(acc2[0][nt*2+1],a0,bt[2],bt[3]);
                MMA(acc2[1][nt*2],  a1,bt[0],bt[1]); MMA(acc2[1][nt*2+1],a1,bt[2],bt[3]);
            }
        }
        __syncthreads();   // all reads of this E buffer done before refill
        if(ch<NCH-2){ load_chunk(sb,ch+2,ch&1,tid); CPA_COMMIT(); }
    }

    // ---- denominator reduce (fixed order -> deterministic) ----
    float* dP=(float*)(smem+OFF_DENP);
    #pragma unroll
    for(int mi=0;mi<2;mi++){
        int rr=32*mg+16*mi+(t>>2);
        dP[rr*16+ng*4+(t&3)]=den[mi][0];
        dP[(rr+8)*16+ng*4+(t&3)]=den[mi][1];
    }
    __syncthreads();
    float* dF=(float*)(smem+OFF_DEN);
    if(tid<TILE_M){
        float s=0.f;
        #pragma unroll
        for(int j=0;j<16;j++) s+=dP[tid*16+j];
        dF[tid]=s;
    }
    __syncthreads();

    // ---- normalize, write out, loss vs fp32 z ----
    float lsum=0.f;
    #pragma unroll
    for(int mi=0;mi<2;mi++){
        int r0=32*mg+16*mi+(t>>2);
        float inv0=1.f/dF[r0], inv1=1.f/dF[r0+8];
        size_t g0=(rowBase+r0)*D, g1=g0+8*(size_t)D;
        #pragma unroll
        for(int j=0;j<8;j++){
            int dc=64*ng+j*8+(t&3)*2;
            float ox0=acc2[mi][j][0]*inv0, oy0=acc2[mi][j][1]*inv0;
            float ox1=acc2[mi][j][2]*inv1, oy1=acc2[mi][j][3]*inv1;
            float2 z0=*(const float2*)(z+g0+dc);
            float2 z1=*(const float2*)(z+g1+dc);
            float d0=ox0-z0.x, d1=oy0-z0.y, d2=ox1-z1.x, d3=oy1-z1.y;
            lsum+=d0*d0+d1*d1+d2*d2+d3*d3;
            *(float2*)(out+g0+dc)=make_float2(ox0,oy0);
            *(float2*)(out+g1+dc)=make_float2(ox1,oy1);
        }
    }
    #pragma unroll
    for(int o=16;o>0;o>>=1) lsum+=__shfl_down_sync(0xffffffffu,lsum,o);
    float* sRed=(float*)(smem+OFF_RED);
    if(t==0) sRed[wid]=lsum;
    __syncthreads();
    if(tid==0){
        float s=0.f;
        #pragma unroll
        for(int w=0;w<16;w++) s+=sRed[w];
        g_block_loss[blockIdx.x]=s;
    }
}

__global__ void loss_finalize(float* __restrict__ out,int nblocks,float inv_nd,int li){
    __shared__ float sh[256];
    int tid=threadIdx.x; float s=0.f;
    for(int i=tid;i<nblocks;i+=256) s+=g_block_loss[i];
    sh[tid]=s; __syncthreads();
    for(int o=128;o>0;o>>=1){ if(tid<o) sh[tid]+=sh[tid+o]; __syncthreads(); }
    if(tid==0) out[li]=sh[0]*inv_nd;
}

extern "C" void kernel_launch(void* const* d_in,const int* in_sizes,int n_in,
                              void* d_out,int out_size){
    const float* z=(const float*)d_in[0];
    const float* cb=(const float*)d_in[1];
    int sz0=in_sizes[0], sz1=in_sizes[1];
    if(sz0<sz1){ const float* tp=z; z=cb; cb=tp; int ts=sz0; sz0=sz1; sz1=ts; }
    float* out=(float*)d_out;
    int nrows=sz0/D, nblocks=nrows/TILE_M;

    cudaFuncSetAttribute(svq_hmma, cudaFuncAttributeMaxDynamicSharedMemorySize, SMEM_TOTAL);
    prep_cb<<<KTOT,256>>>(cb);
    svq_hmma<<<nblocks,THREADS,SMEM_TOTAL>>>(z,out);
    loss_finalize<<<1,256>>>(out,nblocks,1.0f/((float)nrows*(float)D),out_size-1);
}